// round 1
// baseline (speedup 1.0000x reference)
#include <cuda_runtime.h>
#include <cuda_bf16.h>
#include <cstdint>

// Problem dims
#define D_IN  4096
#define D_OUT 4096
#define M_TOT 16384   // 8 * 2048
constexpr int RANK = 16;

// ---------------------------------------------------------------------------
// Scratch (static __device__ arrays — the allowed scratch mechanism)
// ---------------------------------------------------------------------------
__device__ __nv_bfloat16 g_xh[(size_t)M_TOT * D_IN];   // 128 MB
__device__ __nv_bfloat16 g_xl[(size_t)M_TOT * D_IN];   // 128 MB
__device__ __nv_bfloat16 g_kh[(size_t)D_IN * D_OUT];   // 32 MB
__device__ __nv_bfloat16 g_kl[(size_t)D_IN * D_OUT];   // 32 MB

// ---------------------------------------------------------------------------
// Kernel 1: split x (fp32) into bf16 hi + bf16 lo
// ---------------------------------------------------------------------------
__global__ void split_x_kernel(const float4* __restrict__ x) {
    size_t i = (size_t)blockIdx.x * blockDim.x + threadIdx.x;
    float4 v = x[i];
    float vals[4] = {v.x, v.y, v.z, v.w};
    union { __nv_bfloat16 b[4]; float2 f2; } uh, ul;
#pragma unroll
    for (int j = 0; j < 4; j++) {
        __nv_bfloat16 hi = __float2bfloat16_rn(vals[j]);
        float lo = vals[j] - __bfloat162float(hi);
        uh.b[j] = hi;
        ul.b[j] = __float2bfloat16_rn(lo);
    }
    reinterpret_cast<float2*>(g_xh)[i] = uh.f2;
    reinterpret_cast<float2*>(g_xl)[i] = ul.f2;
}

// ---------------------------------------------------------------------------
// Kernel 2: build LoHA kernel matrix  K = W + (1/256) * (a0@b0) ⊙ (a1@b1),
// split into bf16 hi/lo.
// ---------------------------------------------------------------------------
__global__ void build_k_kernel(const float* __restrict__ W,
                               const float* __restrict__ a0,
                               const float* __restrict__ b0,
                               const float* __restrict__ a1,
                               const float* __restrict__ b1) {
    int j = blockIdx.x * blockDim.x + threadIdx.x;   // d_out index (coalesced)
    int i = blockIdx.y;                              // d_in index
    float p0 = 0.f, p1 = 0.f;
#pragma unroll
    for (int r = 0; r < RANK; r++) {
        float a0v = __ldg(&a0[i * RANK + r]);
        float a1v = __ldg(&a1[i * RANK + r]);
        p0 += a0v * __ldg(&b0[r * D_OUT + j]);
        p1 += a1v * __ldg(&b1[r * D_OUT + j]);
    }
    float k = W[(size_t)i * D_OUT + j] + (1.0f / 256.0f) * p0 * p1;
    __nv_bfloat16 hi = __float2bfloat16_rn(k);
    float lo = k - __bfloat162float(hi);
    g_kh[(size_t)i * D_OUT + j] = hi;
    g_kl[(size_t)i * D_OUT + j] = __float2bfloat16_rn(lo);
}

// ---------------------------------------------------------------------------
// GEMM: out[M,N] = xh@Kh + xh@Kl + xl@Kh + bias   (fp32 accumulate)
// 128x128 block tile, BK=32, 8 warps (2 M x 4 N), warp tile 64x32,
// mma.sync.m16n8k16.bf16, cp.async double buffering.
// ---------------------------------------------------------------------------
constexpr int BM = 128, BN = 128, BK = 32;
constexpr int LDA = BK + 8;    // 40 bf16 per A row (pad: conflict-free ldmatrix)
constexpr int LDB = BN + 8;    // 136 bf16 per B row
constexpr int NTILE_M = M_TOT / BM;   // 128
constexpr int NTILE_N = D_OUT / BN;   // 32
constexpr int KTILES = (D_IN / BK) * 3;  // 384 (3 hi/lo product segments)

__device__ __forceinline__ uint32_t smem_u32(const void* p) {
    return (uint32_t)__cvta_generic_to_shared(p);
}
__device__ __forceinline__ void cp16(uint32_t s, const void* g) {
    asm volatile("cp.async.cg.shared.global [%0], [%1], 16;\n" :: "r"(s), "l"(g));
}
__device__ __forceinline__ void ldsm_x4(uint32_t& r0, uint32_t& r1, uint32_t& r2,
                                        uint32_t& r3, uint32_t a) {
    asm volatile("ldmatrix.sync.aligned.m8n8.x4.shared.b16 {%0,%1,%2,%3}, [%4];\n"
                 : "=r"(r0), "=r"(r1), "=r"(r2), "=r"(r3) : "r"(a));
}
__device__ __forceinline__ void ldsm_x4_t(uint32_t& r0, uint32_t& r1, uint32_t& r2,
                                          uint32_t& r3, uint32_t a) {
    asm volatile("ldmatrix.sync.aligned.m8n8.x4.trans.shared.b16 {%0,%1,%2,%3}, [%4];\n"
                 : "=r"(r0), "=r"(r1), "=r"(r2), "=r"(r3) : "r"(a));
}
__device__ __forceinline__ void mma16816(float* c, const uint32_t* a, const uint32_t* b) {
    asm volatile(
        "mma.sync.aligned.m16n8k16.row.col.f32.bf16.bf16.f32 "
        "{%0,%1,%2,%3}, {%4,%5,%6,%7}, {%8,%9}, {%0,%1,%2,%3};\n"
        : "+f"(c[0]), "+f"(c[1]), "+f"(c[2]), "+f"(c[3])
        : "r"(a[0]), "r"(a[1]), "r"(a[2]), "r"(a[3]), "r"(b[0]), "r"(b[1]));
}

__global__ void __launch_bounds__(256)
gemm_kernel(float* __restrict__ out, const float* __restrict__ bias) {
    __shared__ __nv_bfloat16 sA[2][BM * LDA];   // 2 x 10240 B
    __shared__ __nv_bfloat16 sB[2][BK * LDB];   // 2 x 8704 B

    // L2-friendly tile ordering: groups of 16 M-tiles sweep all N-tiles
    int bid = blockIdx.x;
    const int GROUP = 16;
    int gsz = GROUP * NTILE_N;
    int grp_id = bid / gsz, rem = bid % gsz;
    int m0 = (grp_id * GROUP + (rem % GROUP)) * BM;
    int n0 = (rem / GROUP) * BN;

    int tid = threadIdx.x;
    int lane = tid & 31, wid = tid >> 5;
    int wm = (wid & 1) * 64;        // warp M offset (2 warps in M)
    int wn = (wid >> 1) * 32;       // warp N offset (4 warps in N)

    float acc[4][4][4];
#pragma unroll
    for (int mi = 0; mi < 4; mi++)
#pragma unroll
        for (int ni = 0; ni < 4; ni++)
#pragma unroll
            for (int e = 0; e < 4; e++) acc[mi][ni][e] = 0.f;

    auto load_tile = [&](int kk, int buf) {
        int seg = kk >> 7;                 // 0: xh*Kh, 1: xh*Kl, 2: xl*Kh
        int k0 = (kk & 127) * BK;
        const __nv_bfloat16* Ap = (seg == 2) ? g_xl : g_xh;
        const __nv_bfloat16* Bp = (seg == 1) ? g_kl : g_kh;
#pragma unroll
        for (int c = 0; c < 2; c++) {      // A tile: 128x32 bf16 = 512 x 16B
            int chunk = tid + c * 256;
            int row = chunk >> 2, col = (chunk & 3) * 8;
            cp16(smem_u32(&sA[buf][row * LDA + col]),
                 Ap + (size_t)(m0 + row) * D_IN + k0 + col);
        }
#pragma unroll
        for (int c = 0; c < 2; c++) {      // B tile: 32x128 bf16
            int chunk = tid + c * 256;
            int row = chunk >> 4, col = (chunk & 15) * 8;
            cp16(smem_u32(&sB[buf][row * LDB + col]),
                 Bp + (size_t)(k0 + row) * D_OUT + n0 + col);
        }
        asm volatile("cp.async.commit_group;\n");
    };

    auto compute_tile = [&](int buf) {
        uint32_t aB = smem_u32(&sA[buf][0]);
        uint32_t bB = smem_u32(&sB[buf][0]);
#pragma unroll
        for (int ks = 0; ks < BK; ks += 16) {
            uint32_t af[4][4];
#pragma unroll
            for (int mi = 0; mi < 4; mi++) {
                uint32_t addr = aB + 2u * ((uint32_t)(wm + mi * 16 + (lane & 15)) * LDA
                                           + ks + ((lane >> 4) << 3));
                ldsm_x4(af[mi][0], af[mi][1], af[mi][2], af[mi][3], addr);
            }
            uint32_t bf_[4][2];
#pragma unroll
            for (int nh = 0; nh < 2; nh++) {
                uint32_t addr = bB + 2u * ((uint32_t)(ks + (lane & 15)) * LDB
                                           + wn + nh * 16 + ((lane >> 4) << 3));
                uint32_t r0, r1, r2, r3;
                ldsm_x4_t(r0, r1, r2, r3, addr);
                bf_[nh * 2][0] = r0; bf_[nh * 2][1] = r1;
                bf_[nh * 2 + 1][0] = r2; bf_[nh * 2 + 1][1] = r3;
            }
#pragma unroll
            for (int mi = 0; mi < 4; mi++)
#pragma unroll
                for (int ni = 0; ni < 4; ni++)
                    mma16816(acc[mi][ni], af[mi], bf_[ni]);
        }
    };

    load_tile(0, 0);
#pragma unroll 1
    for (int kk = 0; kk < KTILES; kk++) {
        int buf = kk & 1;
        if (kk + 1 < KTILES) {
            load_tile(kk + 1, buf ^ 1);
            asm volatile("cp.async.wait_group 1;\n");
        } else {
            asm volatile("cp.async.wait_group 0;\n");
        }
        __syncthreads();
        compute_tile(buf);
        __syncthreads();
    }

    // Epilogue: add bias, write fp32
    int grp = lane >> 2, q = lane & 3;
#pragma unroll
    for (int ni = 0; ni < 4; ni++) {
        int col = n0 + wn + ni * 8 + q * 2;
        float2 bv = *reinterpret_cast<const float2*>(&bias[col]);
#pragma unroll
        for (int mi = 0; mi < 4; mi++) {
            int row0 = m0 + wm + mi * 16 + grp;
            float2 v0 = {acc[mi][ni][0] + bv.x, acc[mi][ni][1] + bv.y};
            float2 v1 = {acc[mi][ni][2] + bv.x, acc[mi][ni][3] + bv.y};
            *reinterpret_cast<float2*>(&out[(size_t)row0 * D_OUT + col]) = v0;
            *reinterpret_cast<float2*>(&out[(size_t)(row0 + 8) * D_OUT + col]) = v1;
        }
    }
}

// ---------------------------------------------------------------------------
// Entry point (graph-capturable: kernel launches only)
// ---------------------------------------------------------------------------
extern "C" void kernel_launch(void* const* d_in, const int* in_sizes, int n_in,
                              void* d_out, int out_size) {
    const float* x    = (const float*)d_in[0];
    const float* W    = (const float*)d_in[1];
    const float* bias = (const float*)d_in[2];
    const float* a0   = (const float*)d_in[3];
    const float* b0   = (const float*)d_in[4];
    const float* a1   = (const float*)d_in[5];
    const float* b1   = (const float*)d_in[6];
    float* out = (float*)d_out;

    (void)in_sizes; (void)n_in; (void)out_size;

    // 1) split x into bf16 hi/lo
    split_x_kernel<<<(unsigned)(((size_t)M_TOT * D_IN) / 4 / 256), 256>>>(
        (const float4*)x);
    // 2) build LoHA kernel matrix, split into bf16 hi/lo
    build_k_kernel<<<dim3(D_OUT / 256, D_IN), 256>>>(W, a0, b0, a1, b1);
    // 3) triple-product bf16 GEMM with fused bias
    gemm_kernel<<<NTILE_M * NTILE_N, 256>>>(out, bias);
}

// round 3
// speedup vs baseline: 1.3870x; 1.3870x over previous
#include <cuda_runtime.h>
#include <cuda_bf16.h>
#include <cstdint>

#define D_IN  4096
#define D_OUT 4096
#define M_TOT 16384
constexpr int RANK = 16;

// ---------------------------------------------------------------------------
// Scratch
// ---------------------------------------------------------------------------
__device__ __nv_bfloat16 g_xh[(size_t)M_TOT * D_IN];    // x hi, [M,K] K-contig
__device__ __nv_bfloat16 g_xl[(size_t)M_TOT * D_IN];    // x lo
__device__ __nv_bfloat16 g_kh[(size_t)D_OUT * D_IN];    // K^T hi, [N,K] K-contig
__device__ __nv_bfloat16 g_kl[(size_t)D_OUT * D_IN];    // K^T lo

// ---------------------------------------------------------------------------
// Helpers
// ---------------------------------------------------------------------------
__device__ __forceinline__ uint32_t smem_u32(const void* p) {
    return (uint32_t)__cvta_generic_to_shared(p);
}
__device__ __forceinline__ void cp16(uint32_t s, const void* g) {
    asm volatile("cp.async.cg.shared.global [%0], [%1], 16;\n" :: "r"(s), "l"(g));
}
#define CP_COMMIT() asm volatile("cp.async.commit_group;\n")
#define CP_WAIT0()  asm volatile("cp.async.wait_group 0;\n")

__device__ __forceinline__ void ldsm_x4(uint32_t& r0, uint32_t& r1, uint32_t& r2,
                                        uint32_t& r3, uint32_t a) {
    asm volatile("ldmatrix.sync.aligned.m8n8.x4.shared.b16 {%0,%1,%2,%3}, [%4];\n"
                 : "=r"(r0), "=r"(r1), "=r"(r2), "=r"(r3) : "r"(a));
}
__device__ __forceinline__ void mma16816(float* c, const uint32_t* a, const uint32_t* b) {
    asm volatile(
        "mma.sync.aligned.m16n8k16.row.col.f32.bf16.bf16.f32 "
        "{%0,%1,%2,%3}, {%4,%5,%6,%7}, {%8,%9}, {%0,%1,%2,%3};\n"
        : "+f"(c[0]), "+f"(c[1]), "+f"(c[2]), "+f"(c[3])
        : "r"(a[0]), "r"(a[1]), "r"(a[2]), "r"(a[3]), "r"(b[0]), "r"(b[1]));
}

// SW128 swizzle (Swizzle<3,4,3>) on byte offsets within a tile (128B rows)
__device__ __forceinline__ uint32_t swz(uint32_t b) { return b ^ ((b >> 3) & 0x70); }

// ---------------------------------------------------------------------------
// Kernel 1: split x into bf16 hi/lo
// ---------------------------------------------------------------------------
__global__ void split_x_kernel(const float4* __restrict__ x) {
    size_t i = (size_t)blockIdx.x * blockDim.x + threadIdx.x;
    float4 v = x[i];
    float vals[4] = {v.x, v.y, v.z, v.w};
    union { __nv_bfloat16 b[4]; float2 f2; } uh, ul;
#pragma unroll
    for (int j = 0; j < 4; j++) {
        __nv_bfloat16 hi = __float2bfloat16_rn(vals[j]);
        float lo = vals[j] - __bfloat162float(hi);
        uh.b[j] = hi;
        ul.b[j] = __float2bfloat16_rn(lo);
    }
    reinterpret_cast<float2*>(g_xh)[i] = uh.f2;
    reinterpret_cast<float2*>(g_xl)[i] = ul.f2;
}

// ---------------------------------------------------------------------------
// Kernel 2: build K = W + (1/256)(a0@b0)⊙(a1@b1), TRANSPOSED, split hi/lo.
// Output: g_kh[n * D_IN + k]  (K^T, K-major rows — B operand layout).
// ---------------------------------------------------------------------------
__global__ void build_k_kernel(const float* __restrict__ W,
                               const float* __restrict__ a0,
                               const float* __restrict__ b0,
                               const float* __restrict__ a1,
                               const float* __restrict__ b1) {
    __shared__ float s[32][33];
    int i0 = blockIdx.y * 32, j0 = blockIdx.x * 32;
    int tx = threadIdx.x, ty = threadIdx.y;
    int i = i0 + ty, j = j0 + tx;     // i = d_in (k), j = d_out (n)
    float p0 = 0.f, p1 = 0.f;
#pragma unroll
    for (int r = 0; r < RANK; r++) {
        p0 += __ldg(&a0[i * RANK + r]) * __ldg(&b0[r * D_OUT + j]);
        p1 += __ldg(&a1[i * RANK + r]) * __ldg(&b1[r * D_OUT + j]);
    }
    s[ty][tx] = W[(size_t)i * D_OUT + j] + (1.0f / 256.0f) * p0 * p1;
    __syncthreads();
    float v = s[tx][ty];              // value at (i0+tx, j0+ty)
    __nv_bfloat16 hi = __float2bfloat16_rn(v);
    float lo = v - __bfloat162float(hi);
    size_t o = (size_t)(j0 + ty) * D_IN + (i0 + tx);  // [n][k]
    g_kh[o] = hi;
    g_kl[o] = __float2bfloat16_rn(lo);
}

// ---------------------------------------------------------------------------
// Fused triple-product GEMM (mma.sync bf16):
//   out[BM=256 x BN=128 tile] = xh@Kh^T + xh@Kl^T + xl@Kh^T + bias
// BK=64, double-buffered cp.async, 512 threads = 16 warps (4M x 4N), 64x32 warp tile.
// ---------------------------------------------------------------------------
constexpr int BM = 256, BN = 128, BK = 64;
constexpr int NT_M = M_TOT / BM;    // 64
constexpr int NT_N = D_OUT / BN;    // 32
constexpr int NKIT = D_IN / BK;     // 64
constexpr int GROUP = 4;            // M-tiles per L2 group

constexpr int XT_SZ = BM * 128;     // 32 KB: 256 rows x 128 B (64 bf16)
constexpr int KT_SZ = BN * 128;     // 16 KB
constexpr int STAGE_SZ = 2 * XT_SZ + 2 * KT_SZ;   // 96 KB
constexpr int SMEM_BYTES = 2 * STAGE_SZ;          // 192 KB

__global__ void __launch_bounds__(512)
gemm_kernel(float* __restrict__ out, const float* __restrict__ bias) {
    extern __shared__ char smem[];
    const uint32_t sb = smem_u32(smem);
    const int tid = threadIdx.x;
    const int wid = tid >> 5, lane = tid & 31;
    const int wm = (wid >> 2) * 64;   // 4 warps in M
    const int wn = (wid & 3) * 32;    // 4 warps in N

    // L2 grouping: GROUP M-tiles sweep all N-tiles (K^T stays L2-resident)
    const int gsz = GROUP * NT_N;          // 128
    const int grp = blockIdx.x / gsz, rem = blockIdx.x % gsz;
    const int m0 = (grp * GROUP + (rem % GROUP)) * BM;
    const int n0 = (rem / GROUP) * BN;

    const __nv_bfloat16* xh_base = g_xh + (size_t)m0 * D_IN;
    const __nv_bfloat16* xl_base = g_xl + (size_t)m0 * D_IN;
    const __nv_bfloat16* kh_base = g_kh + (size_t)n0 * D_IN;
    const __nv_bfloat16* kl_base = g_kl + (size_t)n0 * D_IN;

    float acc[4][4][4];
#pragma unroll
    for (int mi = 0; mi < 4; mi++)
#pragma unroll
        for (int ni = 0; ni < 4; ni++)
#pragma unroll
            for (int e = 0; e < 4; e++) acc[mi][ni][e] = 0.f;

    // --- loader: per thread 12 x cp16 (X: 4+4 chunks, K: 2+2 chunks) ---
    auto load_tile = [&](int it, int buf) {
        const uint32_t st = sb + buf * STAGE_SZ;
        const int k0 = it * BK;
        // X tiles: 2048 16B-chunks each; chunk c -> row=c>>3, cc=c&7
#pragma unroll
        for (int jc = 0; jc < 4; jc++) {
            int c = tid + jc * 512;
            int row = c >> 3, cc = c & 7;
            size_t src = (size_t)row * D_IN + k0 + cc * 8;
            uint32_t d = swz((uint32_t)(row * 128 + cc * 16));
            cp16(st + d, xh_base + src);
            cp16(st + XT_SZ + d, xl_base + src);
        }
        // K tiles: 1024 chunks each
#pragma unroll
        for (int jc = 0; jc < 2; jc++) {
            int c = tid + jc * 512;
            int row = c >> 3, cc = c & 7;
            size_t src = (size_t)row * D_IN + k0 + cc * 8;
            uint32_t d = swz((uint32_t)(row * 128 + cc * 16));
            cp16(st + 2 * XT_SZ + d, kh_base + src);
            cp16(st + 2 * XT_SZ + KT_SZ + d, kl_base + src);
        }
        CP_COMMIT();
    };

    // ldsm address lanes
    const int a_row = (lane & 15);            // + wm + mi*16
    const int a_kb  = (lane >> 4) << 4;       // 0 or 16 bytes
    const int b_row = (lane & 7) + ((lane >> 4) << 3);   // + wn (n row)
    const int b_kb  = ((lane >> 3) & 1) << 4;

    auto compute_tile = [&](int buf) {
        const uint32_t st = sb + buf * STAGE_SZ;
        const uint32_t sXH = st, sXL = st + XT_SZ;
        const uint32_t sKH = st + 2 * XT_SZ, sKL = st + 2 * XT_SZ + KT_SZ;
#pragma unroll
        for (int ks = 0; ks < BK / 16; ks++) {
            const uint32_t kbase = ks * 32;
            // B frags: hi + lo, n32 -> 2 ldsm.x4 each
            uint32_t bh[4][2], bl[4][2];
#pragma unroll
            for (int g = 0; g < 2; g++) {
                uint32_t off = swz((uint32_t)((wn + g * 16 + b_row) * 128 + kbase + b_kb));
                uint32_t r0, r1, r2, r3;
                ldsm_x4(r0, r1, r2, r3, sKH + off);
                bh[g * 2][0] = r0; bh[g * 2][1] = r1;
                bh[g * 2 + 1][0] = r2; bh[g * 2 + 1][1] = r3;
                ldsm_x4(r0, r1, r2, r3, sKL + off);
                bl[g * 2][0] = r0; bl[g * 2][1] = r1;
                bl[g * 2 + 1][0] = r2; bl[g * 2 + 1][1] = r3;
            }
            // A hi frags + 2 products, then A lo frags + 1 product
            uint32_t af[4][4];
#pragma unroll
            for (int mi = 0; mi < 4; mi++) {
                uint32_t off = swz((uint32_t)((wm + mi * 16 + a_row) * 128 + kbase + a_kb));
                ldsm_x4(af[mi][0], af[mi][1], af[mi][2], af[mi][3], sXH + off);
            }
#pragma unroll
            for (int mi = 0; mi < 4; mi++)
#pragma unroll
                for (int ni = 0; ni < 4; ni++) {
                    mma16816(acc[mi][ni], af[mi], bh[ni]);
                    mma16816(acc[mi][ni], af[mi], bl[ni]);
                }
#pragma unroll
            for (int mi = 0; mi < 4; mi++) {
                uint32_t off = swz((uint32_t)((wm + mi * 16 + a_row) * 128 + kbase + a_kb));
                ldsm_x4(af[mi][0], af[mi][1], af[mi][2], af[mi][3], sXL + off);
            }
#pragma unroll
            for (int mi = 0; mi < 4; mi++)
#pragma unroll
                for (int ni = 0; ni < 4; ni++)
                    mma16816(acc[mi][ni], af[mi], bh[ni]);
        }
    };

    load_tile(0, 0);
#pragma unroll 1
    for (int it = 0; it < NKIT; it++) {
        const int buf = it & 1;
        CP_WAIT0();
        __syncthreads();
        if (it + 1 < NKIT) load_tile(it + 1, buf ^ 1);
        compute_tile(buf);
    }

    // Epilogue: fused bias, float2 stores
    const int gr = lane >> 2, q = lane & 3;
#pragma unroll
    for (int ni = 0; ni < 4; ni++) {
        int col = n0 + wn + ni * 8 + q * 2;
        float2 bv = *reinterpret_cast<const float2*>(&bias[col]);
#pragma unroll
        for (int mi = 0; mi < 4; mi++) {
            int row0 = m0 + wm + mi * 16 + gr;
            float2 v0 = {acc[mi][ni][0] + bv.x, acc[mi][ni][1] + bv.y};
            float2 v1 = {acc[mi][ni][2] + bv.x, acc[mi][ni][3] + bv.y};
            *reinterpret_cast<float2*>(&out[(size_t)row0 * D_OUT + col]) = v0;
            *reinterpret_cast<float2*>(&out[(size_t)(row0 + 8) * D_OUT + col]) = v1;
        }
    }
}

// ---------------------------------------------------------------------------
// Entry
// ---------------------------------------------------------------------------
extern "C" void kernel_launch(void* const* d_in, const int* in_sizes, int n_in,
                              void* d_out, int out_size) {
    const float* x    = (const float*)d_in[0];
    const float* W    = (const float*)d_in[1];
    const float* bias = (const float*)d_in[2];
    const float* a0   = (const float*)d_in[3];
    const float* b0   = (const float*)d_in[4];
    const float* a1   = (const float*)d_in[5];
    const float* b1   = (const float*)d_in[6];
    float* out = (float*)d_out;
    (void)in_sizes; (void)n_in; (void)out_size;

    cudaFuncSetAttribute(gemm_kernel,
                         cudaFuncAttributeMaxDynamicSharedMemorySize, SMEM_BYTES);

    split_x_kernel<<<(unsigned)(((size_t)M_TOT * D_IN) / 4 / 256), 256>>>(
        (const float4*)x);
    build_k_kernel<<<dim3(D_OUT / 32, D_IN / 32), dim3(32, 32)>>>(W, a0, b0, a1, b1);
    gemm_kernel<<<NT_M * NT_N, 512, SMEM_BYTES>>>(out, bias);
}

// round 4
// speedup vs baseline: 3.3417x; 2.4093x over previous
#include <cuda_runtime.h>
#include <cuda_fp16.h>
#include <cstdint>

#define D_IN  4096
#define D_OUT 4096
#define M_TOT 16384
constexpr int RANK = 16;

// ---------------------------------------------------------------------------
// Scratch: fp16 copies of x and K^T
// ---------------------------------------------------------------------------
__device__ __half g_x16[(size_t)M_TOT * D_IN];     // [M,K] K-contig, 128 MB
__device__ __half g_k16[(size_t)D_OUT * D_IN];     // K^T [N,K] K-contig, 32 MB

// ---------------------------------------------------------------------------
// Helpers
// ---------------------------------------------------------------------------
__device__ __forceinline__ uint32_t smem_u32(const void* p) {
    return (uint32_t)__cvta_generic_to_shared(p);
}
__device__ __forceinline__ void cp16(uint32_t s, const void* g) {
    asm volatile("cp.async.cg.shared.global [%0], [%1], 16;\n" :: "r"(s), "l"(g));
}
#define CP_COMMIT() asm volatile("cp.async.commit_group;\n")
#define CP_WAIT2()  asm volatile("cp.async.wait_group 2;\n")

__device__ __forceinline__ void ldsm_x4(uint32_t& r0, uint32_t& r1, uint32_t& r2,
                                        uint32_t& r3, uint32_t a) {
    asm volatile("ldmatrix.sync.aligned.m8n8.x4.shared.b16 {%0,%1,%2,%3}, [%4];\n"
                 : "=r"(r0), "=r"(r1), "=r"(r2), "=r"(r3) : "r"(a));
}
__device__ __forceinline__ void mma16816(float* c, const uint32_t* a, const uint32_t* b) {
    asm volatile(
        "mma.sync.aligned.m16n8k16.row.col.f32.f16.f16.f32 "
        "{%0,%1,%2,%3}, {%4,%5,%6,%7}, {%8,%9}, {%0,%1,%2,%3};\n"
        : "+f"(c[0]), "+f"(c[1]), "+f"(c[2]), "+f"(c[3])
        : "r"(a[0]), "r"(a[1]), "r"(a[2]), "r"(a[3]), "r"(b[0]), "r"(b[1]));
}

// SW128 swizzle on byte offsets within a tile (128-byte rows)
__device__ __forceinline__ uint32_t swz(uint32_t b) { return b ^ ((b >> 3) & 0x70); }

// ---------------------------------------------------------------------------
// Kernel 1: convert x fp32 -> fp16 (8 elements/thread)
// ---------------------------------------------------------------------------
__global__ void cvt_x_kernel(const float4* __restrict__ x) {
    size_t i = (size_t)blockIdx.x * blockDim.x + threadIdx.x;
    float4 v0 = x[2 * i], v1 = x[2 * i + 1];
    union { __half h[8]; uint4 u; } o;
    o.h[0] = __float2half_rn(v0.x); o.h[1] = __float2half_rn(v0.y);
    o.h[2] = __float2half_rn(v0.z); o.h[3] = __float2half_rn(v0.w);
    o.h[4] = __float2half_rn(v1.x); o.h[5] = __float2half_rn(v1.y);
    o.h[6] = __float2half_rn(v1.z); o.h[7] = __float2half_rn(v1.w);
    reinterpret_cast<uint4*>(g_x16)[i] = o.u;
}

// ---------------------------------------------------------------------------
// Kernel 2: build K = W + (1/256)(a0@b0)⊙(a1@b1), transposed, fp16.
// Output: g_k16[n * D_IN + k]  (K^T, K-major — B operand layout).
// ---------------------------------------------------------------------------
__global__ void build_k_kernel(const float* __restrict__ W,
                               const float* __restrict__ a0,
                               const float* __restrict__ b0,
                               const float* __restrict__ a1,
                               const float* __restrict__ b1) {
    __shared__ float s[32][33];
    int i0 = blockIdx.y * 32, j0 = blockIdx.x * 32;
    int tx = threadIdx.x, ty = threadIdx.y;
    int i = i0 + ty, j = j0 + tx;     // i = d_in (k), j = d_out (n)
    float p0 = 0.f, p1 = 0.f;
#pragma unroll
    for (int r = 0; r < RANK; r++) {
        p0 += __ldg(&a0[i * RANK + r]) * __ldg(&b0[r * D_OUT + j]);
        p1 += __ldg(&a1[i * RANK + r]) * __ldg(&b1[r * D_OUT + j]);
    }
    s[ty][tx] = W[(size_t)i * D_OUT + j] + (1.0f / 256.0f) * p0 * p1;
    __syncthreads();
    g_k16[(size_t)(j0 + ty) * D_IN + (i0 + tx)] = __float2half_rn(s[tx][ty]);
}

// ---------------------------------------------------------------------------
// fp16 GEMM: out[BM=256 x BN=128] = x @ K^T + bias
// BK=64, 4-stage cp.async pipeline, 256 threads = 8 warps (4M x 2N), 64x64 warp tile.
// ---------------------------------------------------------------------------
constexpr int BM = 256, BN = 128, BK = 64;
constexpr int NT_M = M_TOT / BM;    // 64
constexpr int NT_N = D_OUT / BN;    // 32
constexpr int NKIT = D_IN / BK;     // 64
constexpr int GROUP = 4;

constexpr int XT_SZ = BM * 128;     // 32 KB (256 rows x 128 B = 64 fp16)
constexpr int KT_SZ = BN * 128;     // 16 KB
constexpr int STAGE_SZ = XT_SZ + KT_SZ;   // 48 KB
constexpr int NSTAGE = 4;
constexpr int SMEM_BYTES = NSTAGE * STAGE_SZ;   // 192 KB

__global__ void __launch_bounds__(256, 1)
gemm_kernel(float* __restrict__ out, const float* __restrict__ bias) {
    extern __shared__ char smem[];
    const uint32_t sb = smem_u32(smem);
    const int tid = threadIdx.x;
    const int wid = tid >> 5, lane = tid & 31;
    const int wm = (wid >> 1) * 64;   // 4 warps in M
    const int wn = (wid & 1) * 64;    // 2 warps in N

    const int gsz = GROUP * NT_N;          // 128
    const int grp = blockIdx.x / gsz, rem = blockIdx.x % gsz;
    const int m0 = (grp * GROUP + (rem % GROUP)) * BM;
    const int n0 = (rem / GROUP) * BN;

    const __half* x_base = g_x16 + (size_t)m0 * D_IN;
    const __half* k_base = g_k16 + (size_t)n0 * D_IN;

    float acc[4][8][4];
#pragma unroll
    for (int mi = 0; mi < 4; mi++)
#pragma unroll
        for (int ni = 0; ni < 8; ni++)
#pragma unroll
            for (int e = 0; e < 4; e++) acc[mi][ni][e] = 0.f;

    // Loader: X 2048 chunks (8/thread), K 1024 chunks (4/thread)
    auto load_tile = [&](int it, int buf) {
        const uint32_t st = sb + buf * STAGE_SZ;
        const int k0 = it * BK;
#pragma unroll
        for (int jc = 0; jc < 8; jc++) {
            int c = tid + jc * 256;
            int row = c >> 3, cc = c & 7;
            cp16(st + swz((uint32_t)(row * 128 + cc * 16)),
                 x_base + (size_t)row * D_IN + k0 + cc * 8);
        }
#pragma unroll
        for (int jc = 0; jc < 4; jc++) {
            int c = tid + jc * 256;
            int row = c >> 3, cc = c & 7;
            cp16(st + XT_SZ + swz((uint32_t)(row * 128 + cc * 16)),
                 k_base + (size_t)row * D_IN + k0 + cc * 8);
        }
        CP_COMMIT();
    };

    const int a_row = lane & 15;
    const int a_kb  = (lane >> 4) << 4;
    const int b_row = (lane & 7) + ((lane >> 4) << 3);
    const int b_kb  = ((lane >> 3) & 1) << 4;

    auto compute_tile = [&](int buf) {
        const uint32_t sX = sb + buf * STAGE_SZ;
        const uint32_t sK = sX + XT_SZ;
#pragma unroll
        for (int ks = 0; ks < BK / 16; ks++) {
            const uint32_t kbase = ks * 32;
            uint32_t bf[8][2];
#pragma unroll
            for (int g = 0; g < 4; g++) {
                uint32_t off = swz((uint32_t)((wn + g * 16 + b_row) * 128 + kbase + b_kb));
                uint32_t r0, r1, r2, r3;
                ldsm_x4(r0, r1, r2, r3, sK + off);
                bf[g * 2][0] = r0;     bf[g * 2][1] = r1;
                bf[g * 2 + 1][0] = r2; bf[g * 2 + 1][1] = r3;
            }
            uint32_t af[4][4];
#pragma unroll
            for (int mi = 0; mi < 4; mi++) {
                uint32_t off = swz((uint32_t)((wm + mi * 16 + a_row) * 128 + kbase + a_kb));
                ldsm_x4(af[mi][0], af[mi][1], af[mi][2], af[mi][3], sX + off);
            }
#pragma unroll
            for (int mi = 0; mi < 4; mi++)
#pragma unroll
                for (int ni = 0; ni < 8; ni++)
                    mma16816(acc[mi][ni], af[mi], bf[ni]);
        }
    };

    load_tile(0, 0);
    load_tile(1, 1);
    load_tile(2, 2);
#pragma unroll 1
    for (int it = 0; it < NKIT; it++) {
        CP_WAIT2();
        __syncthreads();
        if (it + 3 < NKIT) load_tile(it + 3, (it + 3) & 3);
        compute_tile(it & 3);
    }

    // Epilogue: fused bias, float2 stores
    const int gr = lane >> 2, q = lane & 3;
#pragma unroll
    for (int ni = 0; ni < 8; ni++) {
        int col = n0 + wn + ni * 8 + q * 2;
        float2 bv = *reinterpret_cast<const float2*>(&bias[col]);
#pragma unroll
        for (int mi = 0; mi < 4; mi++) {
            int row0 = m0 + wm + mi * 16 + gr;
            float2 v0 = {acc[mi][ni][0] + bv.x, acc[mi][ni][1] + bv.y};
            float2 v1 = {acc[mi][ni][2] + bv.x, acc[mi][ni][3] + bv.y};
            *reinterpret_cast<float2*>(&out[(size_t)row0 * D_OUT + col]) = v0;
            *reinterpret_cast<float2*>(&out[(size_t)(row0 + 8) * D_OUT + col]) = v1;
        }
    }
}

// ---------------------------------------------------------------------------
// Entry
// ---------------------------------------------------------------------------
extern "C" void kernel_launch(void* const* d_in, const int* in_sizes, int n_in,
                              void* d_out, int out_size) {
    const float* x    = (const float*)d_in[0];
    const float* W    = (const float*)d_in[1];
    const float* bias = (const float*)d_in[2];
    const float* a0   = (const float*)d_in[3];
    const float* b0   = (const float*)d_in[4];
    const float* a1   = (const float*)d_in[5];
    const float* b1   = (const float*)d_in[6];
    float* out = (float*)d_out;
    (void)in_sizes; (void)n_in; (void)out_size;

    cudaFuncSetAttribute(gemm_kernel,
                         cudaFuncAttributeMaxDynamicSharedMemorySize, SMEM_BYTES);

    cvt_x_kernel<<<(unsigned)(((size_t)M_TOT * D_IN) / 8 / 256), 256>>>(
        (const float4*)x);
    build_k_kernel<<<dim3(D_OUT / 32, D_IN / 32), dim3(32, 32)>>>(W, a0, b0, a1, b1);
    gemm_kernel<<<NT_M * NT_N, 256, SMEM_BYTES>>>(out, bias);
}